// round 17
// baseline (speedup 1.0000x reference)
#include <cuda_runtime.h>
#include <cuda_bf16.h>
#include <math.h>
#include <stdint.h>

#define Ldim 2048
#define Sdim 2048
#define Nb   2
#define Ed   512
#define Hh   8
#define Dd   64

#define WOFF ((size_t)Ldim * Nb * Ed)   // offset of attn_weights in d_out

// Scratch
__device__ float g_O[(size_t)Nb * Hh * Ldim * Dd];
__device__ float g_rowsum[(size_t)Hh * Nb * Ldim];
__device__ __nv_bfloat16 g_Qh[(size_t)Nb * Hh * Ldim * Dd];
__device__ __nv_bfloat16 g_Ql[(size_t)Nb * Hh * Ldim * Dd];
__device__ __nv_bfloat16 g_Kh[(size_t)Nb * Hh * Sdim * Dd];
__device__ __nv_bfloat16 g_Kl[(size_t)Nb * Hh * Sdim * Dd];
__device__ __nv_bfloat16 g_Vh[(size_t)Nb * Hh * Sdim * Dd];
__device__ __nv_bfloat16 g_Vl[(size_t)Nb * Hh * Sdim * Dd];

// ===================== mma.sync helpers =====================
__device__ __forceinline__ uint32_t smem_u32(const void* p) {
    uint32_t a;
    asm("{ .reg .u64 t; cvta.to.shared.u64 t, %1; cvt.u32.u64 %0, t; }" : "=r"(a) : "l"(p));
    return a;
}

__device__ __forceinline__ void ldsm_x4(uint32_t r[4], uint32_t addr) {
    asm volatile("ldmatrix.sync.aligned.m8n8.x4.shared.b16 {%0,%1,%2,%3}, [%4];"
                 : "=r"(r[0]), "=r"(r[1]), "=r"(r[2]), "=r"(r[3]) : "r"(addr));
}

__device__ __forceinline__ void ldsm_x4_t(uint32_t r[4], uint32_t addr) {
    asm volatile("ldmatrix.sync.aligned.m8n8.x4.trans.shared.b16 {%0,%1,%2,%3}, [%4];"
                 : "=r"(r[0]), "=r"(r[1]), "=r"(r[2]), "=r"(r[3]) : "r"(addr));
}

__device__ __forceinline__ void mma_bf16(float c[4], const uint32_t a[4],
                                         uint32_t b0, uint32_t b1) {
    asm volatile("mma.sync.aligned.m16n8k16.row.col.f32.bf16.bf16.f32 "
                 "{%0,%1,%2,%3}, {%4,%5,%6,%7}, {%8,%9}, {%0,%1,%2,%3};"
                 : "+f"(c[0]), "+f"(c[1]), "+f"(c[2]), "+f"(c[3])
                 : "r"(a[0]), "r"(a[1]), "r"(a[2]), "r"(a[3]), "r"(b0), "r"(b1));
}

#define MM_PITCH 72

// Fused 128x128 split-bf16 inner product over a 64-wide K chunk.
__device__ __forceinline__ void mma_block_fused(
    uint32_t uAh, uint32_t uAl, uint32_t uBh, uint32_t uBl,
    int arow, int acol, int brow, int bcol, float acc[2][8][4])
{
    #pragma unroll
    for (int k0 = 0; k0 < 64; k0 += 16) {
        uint32_t aH[2][4], aL[2][4];
        #pragma unroll
        for (int mt = 0; mt < 2; ++mt) {
            uint32_t aoff = (uint32_t)(((arow + mt * 16) * MM_PITCH) + k0 + acol) * 2;
            ldsm_x4(aH[mt], uAh + aoff);
            ldsm_x4(aL[mt], uAl + aoff);
        }
        #pragma unroll
        for (int np = 0; np < 4; ++np) {
            uint32_t boff = (uint32_t)(((brow + np * 16) * MM_PITCH) + k0 + bcol) * 2;
            uint32_t bH[4], bL[4];
            ldsm_x4(bH, uBh + boff);
            ldsm_x4(bL, uBl + boff);
            #pragma unroll
            for (int mt = 0; mt < 2; ++mt) {
                mma_bf16(acc[mt][np*2+0], aH[mt], bH[0], bH[1]);
                mma_bf16(acc[mt][np*2+1], aH[mt], bH[2], bH[3]);
                mma_bf16(acc[mt][np*2+0], aH[mt], bL[0], bL[1]);
                mma_bf16(acc[mt][np*2+1], aH[mt], bL[2], bL[3]);
                mma_bf16(acc[mt][np*2+0], aL[mt], bH[0], bH[1]);
                mma_bf16(acc[mt][np*2+1], aL[mt], bH[2], bH[3]);
            }
        }
    }
}

#define MM_TILE (128 * MM_PITCH)
#define MM_SMEM_BYTES (4 * MM_TILE * 2)   // 73728 bytes

// Stage a 128x64 fp32 gmem tile as split bf16 hi/lo into smem (pitch MM_PITCH).
__device__ __forceinline__ void stage_split(
    const float* src, size_t srcStride,
    __nv_bfloat16* dh, __nv_bfloat16* dl, int tid)
{
    #pragma unroll
    for (int i = 0; i < 8; ++i) {
        int idx = tid + i * 256;                // 0..2047
        int row = idx >> 4, c4 = idx & 15;      // 16 float4 per row
        float4 v = *(const float4*)(src + (size_t)row * srcStride + c4 * 4);
        __nv_bfloat16 h0 = __float2bfloat16(v.x);
        __nv_bfloat16 h1 = __float2bfloat16(v.y);
        __nv_bfloat16 h2 = __float2bfloat16(v.z);
        __nv_bfloat16 h3 = __float2bfloat16(v.w);
        __nv_bfloat16* ph = dh + row * MM_PITCH + c4 * 4;
        __nv_bfloat16* pl = dl + row * MM_PITCH + c4 * 4;
        ph[0] = h0; ph[1] = h1; ph[2] = h2; ph[3] = h3;
        pl[0] = __float2bfloat16(v.x - __bfloat162float(h0));
        pl[1] = __float2bfloat16(v.y - __bfloat162float(h1));
        pl[2] = __float2bfloat16(v.z - __bfloat162float(h2));
        pl[3] = __float2bfloat16(v.w - __bfloat162float(h3));
    }
}

// ---------------------------------------------------------------------------
// Zero the per-row softmax denominators (32768 floats).
// ---------------------------------------------------------------------------
__global__ void zero_rowsum_kernel()
{
    int i = blockIdx.x * 256 + threadIdx.x;
    ((float4*)g_rowsum)[i] = make_float4(0.f, 0.f, 0.f, 0.f);
}

// ---------------------------------------------------------------------------
// Projection via mma.sync: C[m,j] = X[m,:]·W[j,:] + b[j], m=(t,n).
// ---------------------------------------------------------------------------
__global__ void __launch_bounds__(256)
proj_mma_kernel(const float* __restrict__ X,
                const float* __restrict__ W,
                const float* __restrict__ bias,
                __nv_bfloat16* __restrict__ outh,
                __nv_bfloat16* __restrict__ outl)
{
    extern __shared__ __nv_bfloat16 sm[];
    __nv_bfloat16* tAh = sm;
    __nv_bfloat16* tAl = sm + MM_TILE;
    __nv_bfloat16* tBh = sm + 2 * MM_TILE;
    __nv_bfloat16* tBl = sm + 3 * MM_TILE;

    const int tid  = threadIdx.x;
    const int lane = tid & 31;
    const int wid  = tid >> 5;
    const int wr   = wid & 3;
    const int wc   = wid >> 2;
    const int m0 = blockIdx.y * 128;
    const int j0 = blockIdx.x * 128;

    float acc[2][8][4];
    #pragma unroll
    for (int mt = 0; mt < 2; ++mt)
        #pragma unroll
        for (int nt = 0; nt < 8; ++nt)
            #pragma unroll
            for (int e = 0; e < 4; ++e) acc[mt][nt][e] = 0.f;

    const int arow = wr * 32 + (lane & 15);
    const int acol = (lane >> 4) * 8;
    const int brow = wc * 64 + (lane & 7) + ((lane >> 4) << 3);
    const int bcol = lane & 8;
    const uint32_t uAh = smem_u32(tAh), uAl = smem_u32(tAl);
    const uint32_t uBh = smem_u32(tBh), uBl = smem_u32(tBl);

    for (int kt = 0; kt < Ed; kt += 64) {
        __syncthreads();
        stage_split(X + (size_t)m0 * Ed + kt, Ed, tAh, tAl, tid);
        stage_split(W + (size_t)j0 * Ed + kt, Ed, tBh, tBl, tid);
        __syncthreads();
        mma_block_fused(uAh, uAl, uBh, uBl, arow, acol, brow, bcol, acc);
    }

    const int g = lane >> 2, q = lane & 3;
    #pragma unroll
    for (int mt = 0; mt < 2; ++mt) {
        #pragma unroll
        for (int nt = 0; nt < 8; ++nt) {
            int mrow = m0 + wr * 32 + mt * 16 + g;
            int col  = j0 + wc * 64 + nt * 8 + q * 2;
            float2 b2 = *(const float2*)(bias + col);
            int h = col >> 6, d = col & 63;
            #pragma unroll
            for (int half = 0; half < 2; ++half) {
                int m = mrow + half * 8;
                int t = m >> 1, n = m & 1;
                float v0 = acc[mt][nt][half * 2 + 0] + b2.x;
                float v1 = acc[mt][nt][half * 2 + 1] + b2.y;
                __nv_bfloat16 h0 = __float2bfloat16(v0);
                __nv_bfloat16 h1 = __float2bfloat16(v1);
                __nv_bfloat162 hv; hv.x = h0; hv.y = h1;
                __nv_bfloat162 lv;
                lv.x = __float2bfloat16(v0 - __bfloat162float(h0));
                lv.y = __float2bfloat16(v1 - __bfloat162float(h1));
                size_t o = (((size_t)n * Hh + h) * Ldim + t) * Dd + d;
                *(__nv_bfloat162*)(outh + o) = hv;
                *(__nv_bfloat162*)(outl + o) = lv;
            }
        }
    }
}

// ---------------------------------------------------------------------------
// Output projection via mma.sync.
// ---------------------------------------------------------------------------
__global__ void __launch_bounds__(256)
oproj_mma_kernel(const float* __restrict__ Wo,
                 const float* __restrict__ bo,
                 float* __restrict__ out)
{
    extern __shared__ __nv_bfloat16 sm[];
    __nv_bfloat16* tAh = sm;
    __nv_bfloat16* tAl = sm + MM_TILE;
    __nv_bfloat16* tBh = sm + 2 * MM_TILE;
    __nv_bfloat16* tBl = sm + 3 * MM_TILE;

    const int tid  = threadIdx.x;
    const int lane = tid & 31;
    const int wid  = tid >> 5;
    const int wr   = wid & 3;
    const int wc   = wid >> 2;
    const int m0 = blockIdx.y * 128;
    const int j0 = blockIdx.x * 128;

    float acc[2][8][4];
    #pragma unroll
    for (int mt = 0; mt < 2; ++mt)
        #pragma unroll
        for (int nt = 0; nt < 8; ++nt)
            #pragma unroll
            for (int e = 0; e < 4; ++e) acc[mt][nt][e] = 0.f;

    const int arow = wr * 32 + (lane & 15);
    const int acol = (lane >> 4) * 8;
    const int brow = wc * 64 + (lane & 7) + ((lane >> 4) << 3);
    const int bcol = lane & 8;
    const uint32_t uAh = smem_u32(tAh), uAl = smem_u32(tAl);
    const uint32_t uBh = smem_u32(tBh), uBl = smem_u32(tBl);

    for (int kt = 0; kt < Ed; kt += 64) {
        __syncthreads();
        {
            const int hsel = kt >> 6;
            #pragma unroll
            for (int i = 0; i < 8; ++i) {
                int idx = tid + i * 256;
                int row = idx >> 4, c4 = idx & 15;
                int m = m0 + row;
                int l = m >> 1, nn = m & 1;
                const float* src = g_O + (((size_t)nn * Hh + hsel) * Ldim + l) * Dd + c4 * 4;
                float4 v = *(const float4*)src;
                __nv_bfloat16 h0 = __float2bfloat16(v.x);
                __nv_bfloat16 h1 = __float2bfloat16(v.y);
                __nv_bfloat16 h2 = __float2bfloat16(v.z);
                __nv_bfloat16 h3 = __float2bfloat16(v.w);
                __nv_bfloat16* ph = tAh + row * MM_PITCH + c4 * 4;
                __nv_bfloat16* pl = tAl + row * MM_PITCH + c4 * 4;
                ph[0] = h0; ph[1] = h1; ph[2] = h2; ph[3] = h3;
                pl[0] = __float2bfloat16(v.x - __bfloat162float(h0));
                pl[1] = __float2bfloat16(v.y - __bfloat162float(h1));
                pl[2] = __float2bfloat16(v.z - __bfloat162float(h2));
                pl[3] = __float2bfloat16(v.w - __bfloat162float(h3));
            }
        }
        stage_split(Wo + (size_t)j0 * Ed + kt, Ed, tBh, tBl, tid);
        __syncthreads();
        mma_block_fused(uAh, uAl, uBh, uBl, arow, acol, brow, bcol, acc);
    }

    const int g = lane >> 2, q = lane & 3;
    #pragma unroll
    for (int mt = 0; mt < 2; ++mt) {
        #pragma unroll
        for (int nt = 0; nt < 8; ++nt) {
            int mrow = m0 + wr * 32 + mt * 16 + g;
            int col  = j0 + wc * 64 + nt * 8 + q * 2;
            float2 b2 = *(const float2*)(bo + col);
            *(float2*)(out + (size_t)mrow * Ed + col) =
                make_float2(acc[mt][nt][0] + b2.x, acc[mt][nt][1] + b2.y);
            *(float2*)(out + (size_t)(mrow + 8) * Ed + col) =
                make_float2(acc[mt][nt][2] + b2.x, acc[mt][nt][3] + b2.y);
        }
    }
}

// ---------------------------------------------------------------------------
// qk via mma.sync split precision. Epilogue writes exp(logit) (unnormalized
// softmax numerator; logits are O(8) so fp32 exp is safe) and accumulates
// per-row partial sums into g_rowsum via quad-reduced atomics.
// ---------------------------------------------------------------------------
__global__ void __launch_bounds__(256)
qk_mma_kernel(const float* __restrict__ attn_bias, float* __restrict__ wout)
{
    extern __shared__ __nv_bfloat16 qs[];
    const int tid  = threadIdx.x;
    const int lane = tid & 31;
    const int wid  = tid >> 5;
    const int wr   = wid & 3;
    const int wc   = wid >> 2;
    const int s0 = blockIdx.x * 128;
    const int l0 = blockIdx.y * 128;
    const int z  = blockIdx.z;
    const int h = z / Nb, n = z % Nb;

    __nv_bfloat16* tQh = qs;
    __nv_bfloat16* tQl = qs + MM_TILE;
    __nv_bfloat16* tKh = qs + 2 * MM_TILE;
    __nv_bfloat16* tKl = qs + 3 * MM_TILE;

    const size_t qoff = ((size_t)(n * Hh + h) * Ldim + l0) * Dd;
    const size_t koff = ((size_t)(n * Hh + h) * Sdim + s0) * Dd;
    {
        const uint4* srcs[4] = {
            (const uint4*)(g_Qh + qoff), (const uint4*)(g_Ql + qoff),
            (const uint4*)(g_Kh + koff), (const uint4*)(g_Kl + koff)
        };
        __nv_bfloat16* dsts[4] = { tQh, tQl, tKh, tKl };
        #pragma unroll
        for (int t = 0; t < 4; ++t) {
            const uint4* s = srcs[t];
            __nv_bfloat16* d = dsts[t];
            #pragma unroll
            for (int i = 0; i < 4; ++i) {
                int e = tid + i * 256;
                int row = e >> 3, c = e & 7;
                *(uint4*)(d + row * MM_PITCH + c * 8) = s[row * 8 + c];
            }
        }
    }
    __syncthreads();

    float acc[2][8][4];
    #pragma unroll
    for (int mt = 0; mt < 2; ++mt)
        #pragma unroll
        for (int nt = 0; nt < 8; ++nt)
            #pragma unroll
            for (int e = 0; e < 4; ++e) acc[mt][nt][e] = 0.f;

    const int arow = wr * 32 + (lane & 15);
    const int acol = (lane >> 4) * 8;
    const int brow = wc * 64 + (lane & 7) + ((lane >> 4) << 3);
    const int bcol = lane & 8;

    mma_block_fused(smem_u32(tQh), smem_u32(tQl), smem_u32(tKh), smem_u32(tKl),
                    arow, acol, brow, bcol, acc);

    const int g = lane >> 2, q = lane & 3;
    float rs[2][2] = {};   // [mt][half] partial row sums over this warp's 64 cols
    #pragma unroll
    for (int mt = 0; mt < 2; ++mt) {
        #pragma unroll
        for (int nt = 0; nt < 8; ++nt) {
            int row = l0 + wr * 32 + mt * 16 + g;
            int col = s0 + wc * 64 + nt * 8 + q * 2;
            const float* bp = attn_bias + (size_t)row * Sdim + col;
            float* op = wout + ((size_t)z * Ldim + row) * Sdim + col;
            float2 b0 = *(const float2*)bp;
            float2 b8 = *(const float2*)(bp + 8 * Sdim);
            float e0 = __expf(fmaf(acc[mt][nt][0], 0.125f, b0.x));
            float e1 = __expf(fmaf(acc[mt][nt][1], 0.125f, b0.y));
            float e2 = __expf(fmaf(acc[mt][nt][2], 0.125f, b8.x));
            float e3 = __expf(fmaf(acc[mt][nt][3], 0.125f, b8.y));
            *(float2*)op = make_float2(e0, e1);
            *(float2*)(op + 8 * Sdim) = make_float2(e2, e3);
            rs[mt][0] += e0 + e1;
            rs[mt][1] += e2 + e3;
        }
    }
    // Quad reduce (lanes g*4+q, q=0..3 share a row) then atomicAdd.
    float* rsb = g_rowsum + (size_t)z * Ldim;
    #pragma unroll
    for (int mt = 0; mt < 2; ++mt) {
        #pragma unroll
        for (int half = 0; half < 2; ++half) {
            float v = rs[mt][half];
            v += __shfl_xor_sync(0xffffffffu, v, 1);
            v += __shfl_xor_sync(0xffffffffu, v, 2);
            if (q == 0) {
                int row = l0 + wr * 32 + mt * 16 + g + half * 8;
                atomicAdd(rsb + row, v);
            }
        }
    }
}

// ---------------------------------------------------------------------------
// PV via mma.sync split precision. Normalizes P by the softmax denominator
// during staging and writes the normalized weights back to wts (the required
// attn_weights output).
// ---------------------------------------------------------------------------
#define PV_P_TILE (128 * MM_PITCH)
#define PV_V_TILE (64 * MM_PITCH)
#define PV_SMEM_BYTES ((2 * PV_P_TILE + 2 * PV_V_TILE) * 2)   // 55296 bytes

__global__ void __launch_bounds__(256)
pv_mma_kernel(float* __restrict__ wts)
{
    extern __shared__ __nv_bfloat16 ps[];
    __shared__ float invS[128];
    const int tid  = threadIdx.x;
    const int lane = tid & 31;
    const int wid  = tid >> 5;
    const int wr   = wid & 3;
    const int wc   = wid >> 2;
    const int l0 = blockIdx.x * 128;
    const int z  = blockIdx.y;
    const int h = z / Nb, n = z % Nb;

    __nv_bfloat16* Ph = ps;
    __nv_bfloat16* Pl = ps + PV_P_TILE;
    __nv_bfloat16* Vh = ps + 2 * PV_P_TILE;
    __nv_bfloat16* Vl = ps + 2 * PV_P_TILE + PV_V_TILE;

    float* Pb = wts + (size_t)z * Ldim * Sdim;
    const __nv_bfloat16* Vhb = g_Vh + (size_t)(n * Hh + h) * Sdim * Dd;
    const __nv_bfloat16* Vlb = g_Vl + (size_t)(n * Hh + h) * Sdim * Dd;

    if (tid < 128)
        invS[tid] = 1.0f / g_rowsum[(size_t)z * Ldim + l0 + tid];

    float acc[2][4][4];
    #pragma unroll
    for (int mt = 0; mt < 2; ++mt)
        #pragma unroll
        for (int nt = 0; nt < 4; ++nt)
            #pragma unroll
            for (int e = 0; e < 4; ++e) acc[mt][nt][e] = 0.f;

    const int arow = wr * 32 + (lane & 15);
    const int acol = (lane >> 4) * 8;
    const int vkrow = (lane & 7) + ((lane >> 3) & 1) * 8;
    const int vcol  = wc * 32 + (lane >> 4) * 8;

    const uint32_t uPh = smem_u32(Ph), uPl = smem_u32(Pl);
    const uint32_t uVh = smem_u32(Vh), uVl = smem_u32(Vl);

    for (int s0 = 0; s0 < Sdim; s0 += 64) {
        __syncthreads();
        #pragma unroll
        for (int i = 0; i < 8; ++i) {
            int idx = tid + i * 256;
            int row = idx >> 4, c4 = idx & 15;
            float* src = Pb + (size_t)(l0 + row) * Sdim + s0 + c4 * 4;
            float4 v = *(const float4*)src;
            float sc = invS[row];
            v.x *= sc; v.y *= sc; v.z *= sc; v.w *= sc;
            *(float4*)src = v;                       // normalized attn_weights
            __nv_bfloat16 h0 = __float2bfloat16(v.x);
            __nv_bfloat16 h1 = __float2bfloat16(v.y);
            __nv_bfloat16 h2 = __float2bfloat16(v.z);
            __nv_bfloat16 h3 = __float2bfloat16(v.w);
            __nv_bfloat16* dh = Ph + row * MM_PITCH + c4 * 4;
            __nv_bfloat16* dl = Pl + row * MM_PITCH + c4 * 4;
            dh[0] = h0; dh[1] = h1; dh[2] = h2; dh[3] = h3;
            dl[0] = __float2bfloat16(v.x - __bfloat162float(h0));
            dl[1] = __float2bfloat16(v.y - __bfloat162float(h1));
            dl[2] = __float2bfloat16(v.z - __bfloat162float(h2));
            dl[3] = __float2bfloat16(v.w - __bfloat162float(h3));
        }
        #pragma unroll
        for (int i = 0; i < 2; ++i) {
            int idx = tid + i * 256;
            int row = idx >> 3, c = idx & 7;
            *(uint4*)(Vh + row * MM_PITCH + c * 8) =
                ((const uint4*)(Vhb + (size_t)(s0 + row) * Dd))[c];
            *(uint4*)(Vl + row * MM_PITCH + c * 8) =
                ((const uint4*)(Vlb + (size_t)(s0 + row) * Dd))[c];
        }
        __syncthreads();

        #pragma unroll
        for (int k0 = 0; k0 < 64; k0 += 16) {
            uint32_t aH[2][4], aL[2][4];
            #pragma unroll
            for (int mt = 0; mt < 2; ++mt) {
                ldsm_x4(aH[mt], uPh + (uint32_t)(((arow + mt * 16) * MM_PITCH) + k0 + acol) * 2);
                ldsm_x4(aL[mt], uPl + (uint32_t)(((arow + mt * 16) * MM_PITCH) + k0 + acol) * 2);
            }
            #pragma unroll
            for (int ng = 0; ng < 2; ++ng) {
                uint32_t bH[4], bL[4];
                uint32_t voff = (uint32_t)(((k0 + vkrow) * MM_PITCH) + vcol + ng * 16) * 2;
                ldsm_x4_t(bH, uVh + voff);
                ldsm_x4_t(bL, uVl + voff);
                #pragma unroll
                for (int mt = 0; mt < 2; ++mt) {
                    mma_bf16(acc[mt][ng*2+0], aH[mt], bH[0], bH[1]);
                    mma_bf16(acc[mt][ng*2+1], aH[mt], bH[2], bH[3]);
                    mma_bf16(acc[mt][ng*2+0], aH[mt], bL[0], bL[1]);
                    mma_bf16(acc[mt][ng*2+1], aH[mt], bL[2], bL[3]);
                    mma_bf16(acc[mt][ng*2+0], aL[mt], bH[0], bH[1]);
                    mma_bf16(acc[mt][ng*2+1], aL[mt], bH[2], bH[3]);
                }
            }
        }
    }

    const int g = lane >> 2, q = lane & 3;
    float* Ob = g_O + (size_t)(n * Hh + h) * Ldim * Dd;
    #pragma unroll
    for (int mt = 0; mt < 2; ++mt) {
        #pragma unroll
        for (int nt = 0; nt < 4; ++nt) {
            int row = l0 + wr * 32 + mt * 16 + g;
            int col = wc * 32 + nt * 8 + q * 2;
            *(float2*)(Ob + (size_t)row * Dd + col) =
                make_float2(acc[mt][nt][0], acc[mt][nt][1]);
            *(float2*)(Ob + (size_t)(row + 8) * Dd + col) =
                make_float2(acc[mt][nt][2], acc[mt][nt][3]);
        }
    }
}

// ---------------------------------------------------------------------------
extern "C" void kernel_launch(void* const* d_in, const int* in_sizes, int n_in,
                              void* d_out, int out_size)
{
    const float* query     = (const float*)d_in[0];
    const float* key       = (const float*)d_in[1];
    const float* value     = (const float*)d_in[2];
    const float* attn_bias = (const float*)d_in[3];
    const float* Wq = (const float*)d_in[4];
    const float* bq = (const float*)d_in[5];
    const float* Wk = (const float*)d_in[6];
    const float* bk = (const float*)d_in[7];
    const float* Wv = (const float*)d_in[8];
    const float* bv = (const float*)d_in[9];
    const float* Wo = (const float*)d_in[10];
    const float* bo = (const float*)d_in[11];

    float* out = (float*)d_out;
    float* wts = out + WOFF;

    void *pQh, *pQl, *pKh, *pKl, *pVh, *pVl;
    cudaGetSymbolAddress(&pQh, g_Qh);
    cudaGetSymbolAddress(&pQl, g_Ql);
    cudaGetSymbolAddress(&pKh, g_Kh);
    cudaGetSymbolAddress(&pKl, g_Kl);
    cudaGetSymbolAddress(&pVh, g_Vh);
    cudaGetSymbolAddress(&pVl, g_Vl);

    cudaFuncSetAttribute(proj_mma_kernel,
                         cudaFuncAttributeMaxDynamicSharedMemorySize, MM_SMEM_BYTES);
    cudaFuncSetAttribute(oproj_mma_kernel,
                         cudaFuncAttributeMaxDynamicSharedMemorySize, MM_SMEM_BYTES);
    cudaFuncSetAttribute(qk_mma_kernel,
                         cudaFuncAttributeMaxDynamicSharedMemorySize, MM_SMEM_BYTES);
    cudaFuncSetAttribute(pv_mma_kernel,
                         cudaFuncAttributeMaxDynamicSharedMemorySize, PV_SMEM_BYTES);

    zero_rowsum_kernel<<<dim3(32), dim3(256)>>>();    // 32*256*4 floats = 32768

    dim3 gmm(Ed / 128, (Ldim * Nb) / 128);            // (4, 32)
    proj_mma_kernel<<<gmm, dim3(256), MM_SMEM_BYTES>>>(query, Wq, bq,
        (__nv_bfloat16*)pQh, (__nv_bfloat16*)pQl);
    proj_mma_kernel<<<gmm, dim3(256), MM_SMEM_BYTES>>>(key, Wk, bk,
        (__nv_bfloat16*)pKh, (__nv_bfloat16*)pKl);
    proj_mma_kernel<<<gmm, dim3(256), MM_SMEM_BYTES>>>(value, Wv, bv,
        (__nv_bfloat16*)pVh, (__nv_bfloat16*)pVl);

    dim3 gqk(Sdim / 128, Ldim / 128, Hh * Nb);        // (16, 16, 16)
    qk_mma_kernel<<<gqk, dim3(256), MM_SMEM_BYTES>>>(attn_bias, wts);

    dim3 gpv(Ldim / 128, Hh * Nb);                    // (16, 16)
    pv_mma_kernel<<<gpv, dim3(256), PV_SMEM_BYTES>>>(wts);

    oproj_mma_kernel<<<gmm, dim3(256), MM_SMEM_BYTES>>>(Wo, bo, out);
}